// round 6
// baseline (speedup 1.0000x reference)
#include <cuda_runtime.h>
#include <cuda_fp16.h>
#include <cstdint>

#define B_ 4
#define S_ 2048
#define D_ 1024
#define H_ 1024

// Scratch (__device__ globals; allocation-free rule)
__device__ __align__(128) __half g_x16[B_ * S_ * D_];          // 16 MB
__device__ __align__(128) __half g_wt16[3 * D_ * H_];          // 6 MB  (W^T, [n][k])
__device__ __align__(128) __half g_q16[B_ * S_ * H_];          // 16 MB
__device__ __align__(128) __half g_k16[B_ * S_ * H_];          // 16 MB
__device__ __align__(128) __half g_vt16[B_ * H_ * S_];         // 16 MB (V^T per batch)
__device__ __align__(128) __half g_s16[(size_t)B_ * S_ * S_];  // 32 MB scores
__device__ __align__(128) __half g_p16[(size_t)B_ * S_ * S_];  // 32 MB probs

__device__ __forceinline__ uint32_t smem_u32(const void* p) {
    uint32_t a;
    asm("{ .reg .u64 t; cvta.to.shared.u64 t, %1; cvt.u32.u64 %0, t; }" : "=r"(a) : "l"(p));
    return a;
}
__device__ __forceinline__ void cp16(uint32_t dst, const void* src) {
    asm volatile("cp.async.ca.shared.global [%0], [%1], 16;" :: "r"(dst), "l"(src));
}
#define LDSM4(r0, r1, r2, r3, a)                                                   \
    asm volatile("ldmatrix.sync.aligned.m8n8.x4.shared.b16 {%0,%1,%2,%3}, [%4];"   \
                 : "=r"(r0), "=r"(r1), "=r"(r2), "=r"(r3) : "r"(a))
__device__ __forceinline__ void mma_f16(float* d, const uint32_t* a, const uint32_t* b) {
    asm volatile(
        "mma.sync.aligned.m16n8k16.row.col.f32.f16.f16.f32 "
        "{%0,%1,%2,%3}, {%4,%5,%6,%7}, {%8,%9}, {%0,%1,%2,%3};"
        : "+f"(d[0]), "+f"(d[1]), "+f"(d[2]), "+f"(d[3])
        : "r"(a[0]), "r"(a[1]), "r"(a[2]), "r"(a[3]), "r"(b[0]), "r"(b[1]));
}

// ---------------------------------------------------------------------------
// fp16 NT GEMM: C = op(alpha * (A @ B^T) + bias)
//   A [M,K] half, B [N,K] half, both K-major. Block 128x128, K-chunk 64,
//   8 warps of 64x32, m16n8k16 HMMA, ldmatrix frags, SW128 smem, 3-stage cp.async.
// EMODE: 0 fp32 out (*alpha)   1 fp16 out (+bias)
//        2 fp16 V^T out (+bias), out[b][n][t]   3 fp16 out (*alpha)
// ---------------------------------------------------------------------------
#define STG_A 16384
#define STG   32768
#define NSTG  3
#define SMEM_SZ (NSTG * STG)

template <int EMODE>
__global__ __launch_bounds__(256, 2) void hgemm(
    const __half* __restrict__ A, const __half* __restrict__ Bm,
    float* __restrict__ Cf, __half* __restrict__ Ch,
    const float* __restrict__ bias,
    float alpha, int K, int ldc,
    long sA_, long sB_, long sC_)
{
    extern __shared__ char smem[];
    const uint32_t sb = smem_u32(smem);

    const int tid  = threadIdx.x;
    const int warp = tid >> 5, lane = tid & 31;
    const int g = lane >> 2, tg = lane & 3;
    const int wm0 = (warp & 1) * 64;
    const int wn0 = (warp >> 1) * 32;
    const int m0 = blockIdx.y << 7, n0 = blockIdx.x << 7;

    const __half* pA = A + (size_t)blockIdx.z * sA_ + (size_t)m0 * K;
    const __half* pB = Bm + (size_t)blockIdx.z * sB_ + (size_t)n0 * K;

    float acc[4][4][4];
#pragma unroll
    for (int i = 0; i < 4; i++)
#pragma unroll
        for (int j = 0; j < 4; j++)
#pragma unroll
            for (int r = 0; r < 4; r++) acc[i][j][r] = 0.f;

    const int NC = K >> 6;

    auto load_stage = [&](int s, int c) {
        const int k0 = c << 6;
        const uint32_t sbase = sb + s * STG;
#pragma unroll
        for (int i = 0; i < 4; i++) {
            int idx = tid + (i << 8);              // 0..1023
            int row = idx >> 3, sub = idx & 7;     // 128 rows x 8 x 16B
            uint32_t off = row * 128 + ((sub * 16) ^ ((row & 7) << 4));
            cp16(sbase + off,         pA + (size_t)row * K + k0 + sub * 8);
            cp16(sbase + STG_A + off, pB + (size_t)row * K + k0 + sub * 8);
        }
    };

    // ldmatrix address components
    const uint32_t mask = (lane & 7) << 4;
    const int selA = (lane >> 4) << 4;             // 0 or 16 bytes
    const int selB = ((lane >> 3) & 1) << 4;
    uint32_t baseA[4], baseB[2];
#pragma unroll
    for (int mt = 0; mt < 4; mt++)
        baseA[mt] = sb + (wm0 + mt * 16 + (lane & 15)) * 128;
#pragma unroll
    for (int p = 0; p < 2; p++)
        baseB[p] = sb + STG_A + (wn0 + p * 16 + (lane & 7) + ((lane >> 4) << 3)) * 128;

    load_stage(0, 0);
    asm volatile("cp.async.commit_group;");
    load_stage(1, 1);
    asm volatile("cp.async.commit_group;");

    int s = 0;
    for (int c = 0; c < NC; c++) {
        asm volatile("cp.async.wait_group 1;");
        __syncthreads();
        if (c + 2 < NC) load_stage((s + 2) % NSTG, c + 2);
        asm volatile("cp.async.commit_group;");

        const uint32_t so = s * STG;
#pragma unroll
        for (int ks = 0; ks < 4; ks++) {
            const uint32_t kk2 = ks * 32;
            const uint32_t koA = (kk2 + selA) ^ mask;
            const uint32_t koB = (kk2 + selB) ^ mask;
            uint32_t af[4][4], bf[4][2];
#pragma unroll
            for (int mt = 0; mt < 4; mt++)
                LDSM4(af[mt][0], af[mt][1], af[mt][2], af[mt][3], baseA[mt] + so + koA);
#pragma unroll
            for (int p = 0; p < 2; p++) {
                uint32_t r0, r1, r2, r3;
                LDSM4(r0, r1, r2, r3, baseB[p] + so + koB);
                bf[2 * p][0] = r0;     bf[2 * p][1] = r1;
                bf[2 * p + 1][0] = r2; bf[2 * p + 1][1] = r3;
            }
#pragma unroll
            for (int mt = 0; mt < 4; mt++)
#pragma unroll
                for (int nt = 0; nt < 4; nt++)
                    mma_f16(acc[mt][nt], af[mt], bf[nt]);
        }
        s = (s + 1) % NSTG;
    }
    __syncthreads();   // mainloop smem dead; safe to reuse for EMODE 2

    // ---- epilogue ----
    if (EMODE == 2) {
        // stage into smem [32][72] half per warp, then coalesced V^T stores
        __half* ep = (__half*)smem + warp * 2304;
#pragma unroll
        for (int nt = 0; nt < 4; nt++) {
            const int ncol = n0 + wn0 + nt * 8 + 2 * tg;
            float2 bv = *(const float2*)&bias[ncol];
#pragma unroll
            for (int mt = 0; mt < 4; mt++)
#pragma unroll
                for (int h = 0; h < 2; h++) {
                    int ml = mt * 16 + g + h * 8;
                    int nl = nt * 8 + 2 * tg;
                    ep[nl * 72 + ml]       = __float2half_rn(acc[mt][nt][2 * h]     + bv.x);
                    ep[(nl + 1) * 72 + ml] = __float2half_rn(acc[mt][nt][2 * h + 1] + bv.y);
                }
        }
        __syncwarp();
        const int bidx = m0 >> 11;
        const int tbase = (m0 & 2047) + wm0 + (lane & 7) * 8;
#pragma unroll
        for (int i = 0; i < 8; i++) {
            int nl = i * 4 + (lane >> 3);
            int nglob = n0 + wn0 + nl;
            uint4 v = *(uint4*)&ep[nl * 72 + (lane & 7) * 8];
            *(uint4*)&Ch[((size_t)(bidx * H_ + nglob)) * S_ + tbase] = v;
        }
    } else {
#pragma unroll
        for (int nt = 0; nt < 4; nt++) {
            const int col = n0 + wn0 + nt * 8 + 2 * tg;
            float2 bv = make_float2(0.f, 0.f);
            if (EMODE == 1) bv = *(const float2*)&bias[col];
#pragma unroll
            for (int mt = 0; mt < 4; mt++)
#pragma unroll
                for (int h = 0; h < 2; h++) {
                    int r = m0 + wm0 + mt * 16 + g + h * 8;
                    float vx = acc[mt][nt][2 * h], vy = acc[mt][nt][2 * h + 1];
                    if (EMODE == 0) {
                        *(float2*)&Cf[(size_t)blockIdx.z * sC_ + (size_t)r * ldc + col] =
                            make_float2(vx * alpha, vy * alpha);
                    } else if (EMODE == 1) {
                        __half2 o = __floats2half2_rn(vx + bv.x, vy + bv.y);
                        *(__half2*)&Ch[(size_t)r * ldc + col] = o;
                    } else { // 3
                        __half2 o = __floats2half2_rn(vx * alpha, vy * alpha);
                        *(__half2*)&Ch[(size_t)blockIdx.z * sC_ + (size_t)r * ldc + col] = o;
                    }
                }
        }
    }
}

// ---------------------------------------------------------------------------
// Prep: fp32 -> fp16 copy; W transpose+convert
// ---------------------------------------------------------------------------
__global__ void f2h(const float* __restrict__ in, __half* __restrict__ out, int n8)
{
    int i = blockIdx.x * blockDim.x + threadIdx.x;
    if (i >= n8) return;
    const float4* s = (const float4*)(in + (size_t)i * 8);
    float4 a = s[0], b = s[1];
    __half2 h0 = __floats2half2_rn(a.x, a.y), h1 = __floats2half2_rn(a.z, a.w);
    __half2 h2 = __floats2half2_rn(b.x, b.y), h3 = __floats2half2_rn(b.z, b.w);
    uint4 o;
    o.x = *(uint32_t*)&h0; o.y = *(uint32_t*)&h1;
    o.z = *(uint32_t*)&h2; o.w = *(uint32_t*)&h3;
    ((uint4*)out)[i] = o;
}

__global__ void wtrans(const float* __restrict__ W, __half* __restrict__ WT)
{
    __shared__ float t[32][33];
    int x = blockIdx.x * 32 + threadIdx.x;   // n
    int y0 = blockIdx.y * 32;                // k
#pragma unroll
    for (int i = 0; i < 4; i++)
        t[threadIdx.y + i * 8][threadIdx.x] = W[(size_t)(y0 + threadIdx.y + i * 8) * H_ + x];
    __syncthreads();
    int n = blockIdx.x * 32;
#pragma unroll
    for (int i = 0; i < 4; i++)
        WT[(size_t)(n + threadIdx.y + i * 8) * D_ + y0 + threadIdx.x] =
            __float2half_rn(t[threadIdx.x][threadIdx.y + i * 8]);
}

// ---------------------------------------------------------------------------
// Softmax: fp16 scores in -> fp16 probs out, fp32 math. One block per row.
// ---------------------------------------------------------------------------
__global__ __launch_bounds__(256) void softmax16(const __half* __restrict__ Sc,
                                                 __half* __restrict__ P)
{
    const uint4* src = (const uint4*)(Sc + (size_t)blockIdx.x * 2048);
    uint4* dst = (uint4*)(P + (size_t)blockIdx.x * 2048);
    const int t = threadIdx.x;

    uint4 raw = src[t];
    __half2 h[4] = { *(__half2*)&raw.x, *(__half2*)&raw.y,
                     *(__half2*)&raw.z, *(__half2*)&raw.w };
    float v[8];
#pragma unroll
    for (int i = 0; i < 4; i++) {
        float2 f = __half22float2(h[i]);
        v[2 * i] = f.x; v[2 * i + 1] = f.y;
    }

    float m = v[0];
#pragma unroll
    for (int i = 1; i < 8; i++) m = fmaxf(m, v[i]);

    __shared__ float red[256];
    red[t] = m;
    __syncthreads();
#pragma unroll
    for (int s2 = 128; s2 > 0; s2 >>= 1) {
        if (t < s2) red[t] = fmaxf(red[t], red[t + s2]);
        __syncthreads();
    }
    m = red[0];
    __syncthreads();

    float sum = 0.f;
#pragma unroll
    for (int i = 0; i < 8; i++) { v[i] = expf(v[i] - m); sum += v[i]; }

    red[t] = sum;
    __syncthreads();
#pragma unroll
    for (int s2 = 128; s2 > 0; s2 >>= 1) {
        if (t < s2) red[t] += red[t + s2];
        __syncthreads();
    }
    float inv = 1.f / red[0];

    __half2 o0 = __floats2half2_rn(v[0] * inv, v[1] * inv);
    __half2 o1 = __floats2half2_rn(v[2] * inv, v[3] * inv);
    __half2 o2 = __floats2half2_rn(v[4] * inv, v[5] * inv);
    __half2 o3 = __floats2half2_rn(v[6] * inv, v[7] * inv);
    uint4 o;
    o.x = *(uint32_t*)&o0; o.y = *(uint32_t*)&o1;
    o.z = *(uint32_t*)&o2; o.w = *(uint32_t*)&o3;
    dst[t] = o;
}

// ---------------------------------------------------------------------------
extern "C" void kernel_launch(void* const* d_in, const int* in_sizes, int n_in,
                              void* d_out, int out_size)
{
    const float* x  = (const float*)d_in[0];
    const float* Wq = (const float*)d_in[1];
    const float* bq = (const float*)d_in[2];
    const float* Wk = (const float*)d_in[3];
    const float* bk = (const float*)d_in[4];
    const float* Wv = (const float*)d_in[5];
    const float* bv = (const float*)d_in[6];
    float* out = (float*)d_out;

    __half *x16, *wt16, *q16, *k16, *vt16, *s16, *p16;
    cudaGetSymbolAddress((void**)&x16, g_x16);
    cudaGetSymbolAddress((void**)&wt16, g_wt16);
    cudaGetSymbolAddress((void**)&q16, g_q16);
    cudaGetSymbolAddress((void**)&k16, g_k16);
    cudaGetSymbolAddress((void**)&vt16, g_vt16);
    cudaGetSymbolAddress((void**)&s16, g_s16);
    cudaGetSymbolAddress((void**)&p16, g_p16);

    static int init = 0;
    if (!init) {
        cudaFuncSetAttribute(hgemm<0>, cudaFuncAttributeMaxDynamicSharedMemorySize, SMEM_SZ);
        cudaFuncSetAttribute(hgemm<1>, cudaFuncAttributeMaxDynamicSharedMemorySize, SMEM_SZ);
        cudaFuncSetAttribute(hgemm<2>, cudaFuncAttributeMaxDynamicSharedMemorySize, SMEM_SZ);
        cudaFuncSetAttribute(hgemm<3>, cudaFuncAttributeMaxDynamicSharedMemorySize, SMEM_SZ);
        init = 1;
    }

    const float inv_dk = 0.03125f;   // 1/sqrt(1024)

    // prep
    f2h<<<(1048576 + 255) / 256, 256>>>(x, x16, 1048576);
    wtrans<<<dim3(32, 32), dim3(32, 8)>>>(Wq, wt16);
    wtrans<<<dim3(32, 32), dim3(32, 8)>>>(Wk, wt16 + 1048576);
    wtrans<<<dim3(32, 32), dim3(32, 8)>>>(Wv, wt16 + 2097152);

    // projections: [8192,1024] @ W^T[1024,1024] (NT) + bias
    dim3 gProj(H_ / 128, (B_ * S_) / 128, 1);
    hgemm<1><<<gProj, 256, SMEM_SZ>>>(x16, wt16,           nullptr, q16, bq,
                                      1.f, D_, H_, 0, 0, 0);
    hgemm<1><<<gProj, 256, SMEM_SZ>>>(x16, wt16 + 1048576, nullptr, k16, bk,
                                      1.f, D_, H_, 0, 0, 0);
    hgemm<2><<<gProj, 256, SMEM_SZ>>>(x16, wt16 + 2097152, nullptr, vt16, bv,
                                      1.f, D_, H_, 0, 0, 0);

    // scores[b] = (q @ k^T)/32 -> fp16 (NT, per batch)
    dim3 gScore(S_ / 128, S_ / 128, B_);
    hgemm<3><<<gScore, 256, SMEM_SZ>>>(q16, k16, nullptr, s16, nullptr,
                                       inv_dk, H_, S_,
                                       (long)S_ * H_, (long)S_ * H_, (long)S_ * S_);

    softmax16<<<B_ * S_, 256>>>(s16, p16);

    // out[b] = probs @ V (NT against V^T, per batch) -> fp32
    dim3 gPV(H_ / 128, S_ / 128, B_);
    hgemm<0><<<gPV, 256, SMEM_SZ>>>(p16, vt16, out, nullptr, nullptr,
                                    1.f, S_, H_,
                                    (long)S_ * S_, (long)S_ * H_, (long)S_ * H_);
}